// round 2
// baseline (speedup 1.0000x reference)
#include <cuda_runtime.h>
#include <math_constants.h>

// Fixed problem shape: x[B=4, C=256, H=200, W=320] float32 -> out[B, H, W] float32
#define Bn 4
#define Cn 256
#define Hn 200
#define Wn 320
#define HWn (Hn * Wn)            // 64000
#define CHWn (Cn * HWn)          // 16384000

#define NEG_INF (-CUDART_INF_F)

// Max over the 9x9 window (clipped at borders) of one channel plane.
// Rows are 16B-aligned, so read 3 aligned float4 per row covering [wa, wa+12)
// which always contains the valid columns [max(w-4,0), min(w+4,W-1)]; mask rest.
__device__ __forceinline__ float window_max(const float* __restrict__ chan,
                                            int h, int w) {
    const int r0 = max(h - 4, 0);
    const int r1 = min(h + 4, Hn - 1);
    const int lo = w - 4;
    const int hi = w + 4;
    int wa = (w - 4) & ~3;
    if (wa < 0) wa = 0;
    if (wa > Wn - 12) wa = Wn - 12;   // 308, stays 16B-aligned

    float nb = NEG_INF;
    for (int r = r0; r <= r1; ++r) {
        const float4* p = reinterpret_cast<const float4*>(chan + r * Wn + wa);
        float4 a = __ldg(p + 0);
        float4 b = __ldg(p + 1);
        float4 c = __ldg(p + 2);
        float v[12] = {a.x, a.y, a.z, a.w, b.x, b.y, b.z, b.w, c.x, c.y, c.z, c.w};
#pragma unroll
        for (int j = 0; j < 12; ++j) {
            const int col = wa + j;
            const bool ok = (col >= lo) && (col <= hi);
            nb = fmaxf(nb, ok ? v[j] : NEG_INF);
        }
    }
    return nb;
}

#define UNR 8

__global__ void __launch_bounds__(Wn, 5)
hard_detection_kernel(const float* __restrict__ x, float* __restrict__ out) {
    const int w = threadIdx.x;   // 0..319
    const int h = blockIdx.x;    // 0..199
    const int b = blockIdx.y;    // 0..3

    const float* __restrict__ xb = x + (size_t)b * CHWn;     // batch base
    const float* __restrict__ xp = xb + h * Wn + w;          // channel-0 element

    // ---- Phase A: branchless depth-wise max / argmax / tie-count ----
    // 8 independent accumulator lanes; loads in each group are branch-free so
    // ptxas front-batches them (high MLP).
    float m[UNR];
    int   a[UNR];
    int   n[UNR];
#pragma unroll
    for (int j = 0; j < UNR; ++j) { m[j] = NEG_INF; a[j] = 0; n[j] = 0; }

#pragma unroll 4
    for (int c0 = 0; c0 < Cn; c0 += UNR) {
        float v[UNR];
#pragma unroll
        for (int j = 0; j < UNR; ++j)
            v[j] = __ldg(xp + (size_t)(c0 + j) * HWn);
#pragma unroll
        for (int j = 0; j < UNR; ++j) {
            const bool gt = v[j] > m[j];
            const bool eq = v[j] == m[j];
            n[j] = gt ? 1 : (n[j] + (eq ? 1 : 0));
            a[j] = gt ? (c0 + j) : a[j];
            m[j] = fmaxf(m[j], v[j]);
        }
    }

    // Tree-merge the 8 accumulators (branchless).
#pragma unroll
    for (int s = UNR / 2; s > 0; s >>= 1) {
#pragma unroll
        for (int j = 0; j < s; ++j) {
            const bool gt = m[j + s] > m[j];
            const bool eq = m[j + s] == m[j];
            n[j] = gt ? n[j + s] : (n[j] + (eq ? n[j + s] : 0));
            a[j] = gt ? a[j + s] : a[j];
            m[j] = fmaxf(m[j], m[j + s]);
        }
    }
    const float mx = m[0];
    const int   am = a[0];
    const int   cn = n[0];

    // ---- Phase B: 9x9 local-max test on the argmax channel only ----
    float res;
    if (cn == 1) {
        const float* chan = xb + (size_t)am * HWn;
        const float nb = window_max(chan, h, w);
        res = (nb <= mx) ? mx : 0.0f;   // nb >= mx always (center included)
    } else {
        // Exact tie path (statistically ~0 pixels, kept for correctness):
        // every channel equal to the max contributes mx if it is also its own
        // 9x9 local max.
        int k = 0;
        for (int c = 0; c < Cn; ++c) {
            const float v = __ldg(xp + (size_t)c * HWn);
            if (v == mx) {
                const float* chan = xb + (size_t)c * HWn;
                if (window_max(chan, h, w) <= mx) k++;
            }
        }
        res = mx * (float)k;
    }

    out[(b * Hn + h) * Wn + w] = res;
}

extern "C" void kernel_launch(void* const* d_in, const int* in_sizes, int n_in,
                              void* d_out, int out_size) {
    const float* x = (const float*)d_in[0];
    float* out = (float*)d_out;
    (void)in_sizes; (void)n_in; (void)out_size;

    dim3 grid(Hn, Bn);   // (200, 4) blocks, one block per output row
    dim3 block(Wn);      // 320 threads, one per output column
    hard_detection_kernel<<<grid, block>>>(x, out);
}

// round 3
// speedup vs baseline: 1.1553x; 1.1553x over previous
#include <cuda_runtime.h>
#include <math_constants.h>

// Fixed problem shape: x[B=4, C=256, H=200, W=320] float32 -> out[B, H, W] float32
#define Bn 4
#define Cn 256
#define Hn 200
#define Wn 320
#define HWn (Hn * Wn)            // 64000
#define CHWn (Cn * HWn)          // 16384000
#define HW4 (HWn / 4)            // 16000 float4 groups per channel plane
#define W4  (Wn / 4)             // 80 float4 groups per row

#define NEG_INF (-CUDART_INF_F)

// Max over the 9x9 window (clipped at borders) of one channel plane.
// Fixed 9 row iterations (rows clamped; duplicates harmless for max) so the
// loop fully unrolls and ptxas can front-batch the 27 independent LDG.128s.
__device__ __forceinline__ float window_max(const float* __restrict__ chan,
                                            int h, int w) {
    const int lo = w - 4;
    const int hi = w + 4;
    int wa = (w - 4) & ~3;
    if (wa < 0) wa = 0;
    if (wa > Wn - 12) wa = Wn - 12;   // 308, stays 16B-aligned

    float nb = NEG_INF;
#pragma unroll
    for (int i = 0; i < 9; ++i) {
        const int r = min(max(h - 4 + i, 0), Hn - 1);
        const float4* p = reinterpret_cast<const float4*>(chan + r * Wn + wa);
        float4 a = __ldg(p + 0);
        float4 b = __ldg(p + 1);
        float4 c = __ldg(p + 2);
        float v[12] = {a.x, a.y, a.z, a.w, b.x, b.y, b.z, b.w, c.x, c.y, c.z, c.w};
#pragma unroll
        for (int j = 0; j < 12; ++j) {
            const int col = wa + j;
            const bool ok = (col >= lo) && (col <= hi);
            nb = fmaxf(nb, ok ? v[j] : NEG_INF);
        }
    }
    return nb;
}

__global__ void __launch_bounds__(128)
hard_detection_kernel(const float* __restrict__ x, float* __restrict__ out) {
    const int t = blockIdx.x * 128 + threadIdx.x;    // 0..63999 (float4 pixel group)
    if (t >= Bn * HW4) return;

    const int b   = t / HW4;
    const int rem = t - b * HW4;                     // float4 index within plane
    const int h   = rem / W4;
    const int w0  = (rem - h * W4) * 4;              // first of 4 pixel columns

    const float* __restrict__ xb = x + (size_t)b * CHWn;
    const float4* __restrict__ xp4 =
        reinterpret_cast<const float4*>(xb) + rem;   // channel-0, this pixel group

    // ---- Phase A: branchless depth-wise max/argmax/tie-count for 4 pixels ----
    float mx[4]; int am[4]; int nc[4];
#pragma unroll
    for (int k = 0; k < 4; ++k) { mx[k] = NEG_INF; am[k] = 0; nc[k] = 0; }

#pragma unroll 2
    for (int c0 = 0; c0 < Cn; c0 += 4) {
        float4 v[4];
#pragma unroll
        for (int j = 0; j < 4; ++j)
            v[j] = __ldg(xp4 + (size_t)(c0 + j) * HW4);
#pragma unroll
        for (int j = 0; j < 4; ++j) {
            const float vv[4] = {v[j].x, v[j].y, v[j].z, v[j].w};
#pragma unroll
            for (int k = 0; k < 4; ++k) {
                const bool gt = vv[k] > mx[k];
                const bool eq = vv[k] == mx[k];
                nc[k] = gt ? 1 : (nc[k] + (eq ? 1 : 0));
                am[k] = gt ? (c0 + j) : am[k];
                mx[k] = fmaxf(mx[k], vv[k]);
            }
        }
    }

    // ---- Phase B: 9x9 local-max test on each pixel's argmax channel ----
    float res[4];
#pragma unroll
    for (int k = 0; k < 4; ++k) {
        const int w = w0 + k;
        if (nc[k] == 1) {
            const float* chan = xb + (size_t)am[k] * HWn;
            const float nb = window_max(chan, h, w);
            res[k] = (nb <= mx[k]) ? mx[k] : 0.0f;   // nb >= mx always
        } else {
            // Exact tie path (statistically ~0 pixels): every channel equal to
            // the max contributes mx if it is also its own 9x9 local max.
            const float* xp = xb + h * Wn + w;
            int cnt = 0;
            for (int c = 0; c < Cn; ++c) {
                const float v = __ldg(xp + (size_t)c * HWn);
                if (v == mx[k]) {
                    const float* chan = xb + (size_t)c * HWn;
                    if (window_max(chan, h, w) <= mx[k]) cnt++;
                }
            }
            res[k] = mx[k] * (float)cnt;
        }
    }

    float4 o = make_float4(res[0], res[1], res[2], res[3]);
    reinterpret_cast<float4*>(out)[t] = o;
}

extern "C" void kernel_launch(void* const* d_in, const int* in_sizes, int n_in,
                              void* d_out, int out_size) {
    const float* x = (const float*)d_in[0];
    float* out = (float*)d_out;
    (void)in_sizes; (void)n_in; (void)out_size;

    const int total = Bn * HW4;          // 64000 threads
    const int block = 128;
    const int grid = (total + block - 1) / block;   // 500 blocks
    hard_detection_kernel<<<grid, block>>>(x, out);
}

// round 4
// speedup vs baseline: 1.1644x; 1.0079x over previous
#include <cuda_runtime.h>
#include <math_constants.h>

// Fixed problem shape: x[B=4, C=256, H=200, W=320] float32 -> out[B, H, W] float32
#define Bn 4
#define Cn 256
#define Hn 200
#define Wn 320
#define HWn (Hn * Wn)            // 64000
#define CHWn (Cn * HWn)          // 16384000
#define HW4 (HWn / 4)            // 16000 float4 groups per channel plane
#define W4  (Wn / 4)             // 80 float4 groups per row

#define NEG_INF (-CUDART_INF_F)
#define TPB   128                // threads per block
#define DEPTH 16                 // cp.async ring depth (power of 2)

// ---- cp.async helpers (LDGSTS: fire-and-forget, guaranteed MLP) ----
__device__ __forceinline__ void cp_async16(void* smem_dst, const void* gsrc) {
    unsigned saddr = (unsigned)__cvta_generic_to_shared(smem_dst);
    asm volatile("cp.async.cg.shared.global [%0], [%1], 16;\n"
                 :: "r"(saddr), "l"(gsrc) : "memory");
}
__device__ __forceinline__ void cp_commit() {
    asm volatile("cp.async.commit_group;\n" ::: "memory");
}
template <int N> __device__ __forceinline__ void cp_wait() {
    asm volatile("cp.async.wait_group %0;\n" :: "n"(N) : "memory");
}

// Max over the 9x9 window (clipped at borders) of one channel plane.
// Fixed 9 row iterations (rows clamped; duplicates harmless under max) so the
// loop fully unrolls; 27 independent LDG.128.
__device__ __forceinline__ float window_max(const float* __restrict__ chan,
                                            int h, int w) {
    const int lo = w - 4;
    const int hi = w + 4;
    int wa = (w - 4) & ~3;
    if (wa < 0) wa = 0;
    if (wa > Wn - 12) wa = Wn - 12;   // 308, stays 16B-aligned

    float nb = NEG_INF;
#pragma unroll
    for (int i = 0; i < 9; ++i) {
        const int r = min(max(h - 4 + i, 0), Hn - 1);
        const float4* p = reinterpret_cast<const float4*>(chan + r * Wn + wa);
        float4 a = __ldg(p + 0);
        float4 b = __ldg(p + 1);
        float4 c = __ldg(p + 2);
        float v[12] = {a.x, a.y, a.z, a.w, b.x, b.y, b.z, b.w, c.x, c.y, c.z, c.w};
#pragma unroll
        for (int j = 0; j < 12; ++j) {
            const int col = wa + j;
            const bool ok = (col >= lo) && (col <= hi);
            nb = fmaxf(nb, ok ? v[j] : NEG_INF);
        }
    }
    return nb;
}

__global__ void __launch_bounds__(TPB)
hard_detection_kernel(const float* __restrict__ x, float* __restrict__ out) {
    __shared__ float4 buf[DEPTH * TPB];          // 32 KB ring, thread-private slots

    const int t = blockIdx.x * TPB + threadIdx.x;   // 0..63999 (exact fit)
    const int b   = t / HW4;
    const int rem = t - b * HW4;                    // float4 index within plane
    const int h   = rem / W4;
    const int w0  = (rem - h * W4) * 4;

    const float* __restrict__ xb = x + (size_t)b * CHWn;
    const float4* __restrict__ src = reinterpret_cast<const float4*>(xb) + rem;

    // ---- prologue: fill DEPTH-1 ring slots ----
#pragma unroll
    for (int c = 0; c < DEPTH - 1; ++c) {
        cp_async16(&buf[c * TPB + threadIdx.x], src + (size_t)c * HW4);
        cp_commit();
    }

    // ---- Phase A: pipelined depth-wise max / argmax / tie-count, 4 pixels ----
    float mx[4]; int am[4]; int nc[4];
#pragma unroll
    for (int k = 0; k < 4; ++k) { mx[k] = NEG_INF; am[k] = 0; nc[k] = 0; }

    for (int c = 0; c < Cn; ++c) {
        const int cp = c + DEPTH - 1;
        if (cp < Cn)
            cp_async16(&buf[(cp & (DEPTH - 1)) * TPB + threadIdx.x],
                       src + (size_t)cp * HW4);
        cp_commit();                 // empty groups at the tail keep counts aligned
        cp_wait<DEPTH - 1>();        // group for channel c is now complete

        const float4 v = buf[(c & (DEPTH - 1)) * TPB + threadIdx.x];
        const float vv[4] = {v.x, v.y, v.z, v.w};
#pragma unroll
        for (int k = 0; k < 4; ++k) {
            const bool gt = vv[k] > mx[k];
            const bool eq = vv[k] == mx[k];
            nc[k] = gt ? 1 : (nc[k] + (eq ? 1 : 0));
            am[k] = gt ? c : am[k];
            mx[k] = fmaxf(mx[k], vv[k]);
        }
    }

    // ---- Phase B: 9x9 local-max test on each pixel's argmax channel ----
    float res[4];
#pragma unroll
    for (int k = 0; k < 4; ++k) {
        const int w = w0 + k;
        if (nc[k] == 1) {
            const float* chan = xb + (size_t)am[k] * HWn;
            const float nb = window_max(chan, h, w);
            res[k] = (nb <= mx[k]) ? mx[k] : 0.0f;   // nb >= mx always
        } else {
            // Exact tie path (statistically ~0 pixels): every channel equal to
            // the max contributes mx if it is also its own 9x9 local max.
            const float* xp = xb + h * Wn + w;
            int cnt = 0;
            for (int c = 0; c < Cn; ++c) {
                const float v = __ldg(xp + (size_t)c * HWn);
                if (v == mx[k]) {
                    const float* chan = xb + (size_t)c * HWn;
                    if (window_max(chan, h, w) <= mx[k]) cnt++;
                }
            }
            res[k] = mx[k] * (float)cnt;
        }
    }

    reinterpret_cast<float4*>(out)[t] = make_float4(res[0], res[1], res[2], res[3]);
}

extern "C" void kernel_launch(void* const* d_in, const int* in_sizes, int n_in,
                              void* d_out, int out_size) {
    const float* x = (const float*)d_in[0];
    float* out = (float*)d_out;
    (void)in_sizes; (void)n_in; (void)out_size;

    const int grid = (Bn * HW4) / TPB;   // 500 blocks, exact cover
    hard_detection_kernel<<<grid, TPB>>>(x, out);
}